// round 14
// baseline (speedup 1.0000x reference)
#include <cuda_runtime.h>
#include <cuda_bf16.h>
#include <math.h>

namespace {

constexpr int NVc = 32;   // x dim
constexpr int MCc = 24;   // constraint rows in A
constexpr int MHc = 20;   // hard rows
constexpr int ITc = 200;  // ADMM iterations (must match reference trajectory)

// per-warp shared layout (floats)
constexpr int OFF_A = 0;            // A: 24 rows, stride 36
constexpr int OFF_M = 864;          // M workspace: 32 x 36
constexpr int OFF_T = 2160;         // t buffer (24 used, pad 32)
constexpr int OFF_R = 2192;         // GJ pivot-row buffer (32, pad 40)
constexpr int OFF_U = 2232;         // x_feas for gradient (32, pad 40)
constexpr int WARPF = 2304;         // 9216 bytes per warp

using ull = unsigned long long;

// ---- packed f32x2 helpers (Blackwell FFMA2 path, PTX-only) ----
__device__ __forceinline__ ull pk2(float lo, float hi) {
    ull r;
    asm("mov.b64 %0, {%1, %2};" : "=l"(r) : "f"(lo), "f"(hi));
    return r;
}
__device__ __forceinline__ float2 upk2(ull v) {
    float lo, hi;
    asm("mov.b64 {%0, %1}, %2;" : "=f"(lo), "=f"(hi) : "l"(v));
    return make_float2(lo, hi);
}
__device__ __forceinline__ ull ffma2(ull a, ull b, ull c) {
    ull d;
    asm("fma.rn.f32x2 %0, %1, %2, %3;" : "=l"(d) : "l"(a), "l"(b), "l"(c));
    return d;
}

// Register-resident Gauss-Jordan inverse of SPD 32x32: lane tid owns row tid.
// buf = 32-float, 16B-aligned smem scratch for pivot-row broadcast.
__device__ __forceinline__ void gj_inv_reg(float row[32], float* buf, int tid) {
#pragma unroll
    for (int k = 0; k < 32; ++k) {
        if (tid == k) {
            float4* b4 = reinterpret_cast<float4*>(buf);
#pragma unroll
            for (int q = 0; q < 8; q++)
                b4[q] = make_float4(row[4 * q], row[4 * q + 1], row[4 * q + 2], row[4 * q + 3]);
        }
        __syncwarp();
        float rk[32];
        {
            const float4* b4 = reinterpret_cast<const float4*>(buf);
#pragma unroll
            for (int q = 0; q < 8; q++) {
                float4 v = b4[q];
                rk[4 * q] = v.x; rk[4 * q + 1] = v.y; rk[4 * q + 2] = v.z; rk[4 * q + 3] = v.w;
            }
        }
        __syncwarp();
        float piv = 1.0f / rk[k];
        float f = (row[k] - ((tid == k) ? 1.0f : 0.0f)) * piv;
#pragma unroll
        for (int j = 0; j < 32; ++j)
            row[j] = fmaf(-f, rk[j], row[j]);
        row[k] = (tid == k) ? piv : -f;
    }
}

__global__ void __launch_bounds__(128, 4)
fw_kernel(const float* __restrict__ x_raw, const float* __restrict__ Ain,
          const float* __restrict__ bin, const float* __restrict__ W1,
          const float* __restrict__ b1v, const float* __restrict__ w2,
          float* __restrict__ out, int P)
{
    __shared__ __align__(16) float smem_all[4 * WARPF];
    const int tid = threadIdx.x & 31;
    const int wid = threadIdx.x >> 5;
    const int p = blockIdx.x * 4 + wid;
    if (p >= P) return;
    float* sw = smem_all + wid * WARPF;

    // ------------------------------------------------------------------
    // Load A (smem rows + packed lane-column apk), b, x_raw
    // ------------------------------------------------------------------
    ull apk[12];   // packed pairs (A[2j][tid], A[2j+1][tid])
    {
        float tmpA[MCc];
        const float* Ap = Ain + (size_t)p * (MCc * NVc);
#pragma unroll
        for (int r = 0; r < MCc; r++) {
            float v = Ap[r * NVc + tid];
            sw[OFF_A + r * 36 + tid] = v;
            tmpA[r] = v;
        }
#pragma unroll
        for (int j = 0; j < 12; j++) apk[j] = pk2(tmpA[2 * j], tmpA[2 * j + 1]);
    }
    const float b_own = (tid < MCc) ? bin[(size_t)p * MCc + tid] : 0.0f;
    const float xr = x_raw[(size_t)p * NVc + tid];
    __syncwarp();

    float xf_own = 0.0f, u_own = 0.0f, g_own = 0.0f;

    // ==================================================================
    //  phase 0: anchor QP (Schur-reduced, Ks = A_h^T A_h + .75 A_s^T A_s + 2I)
    //  phase 1: LMO LP   (K = A^T A + I), preceded by the critic gradient
    // ==================================================================
#pragma unroll 1
    for (int phase = 0; phase < 2; ++phase) {
        if (phase == 1) {
            // ----------------------------------------------------------
            // Gradient of critic: g = W1 @ (w2 * (1 - tanh^2(x W1 + b1)))
            // ----------------------------------------------------------
            float gp[32];
#pragma unroll
            for (int j = 0; j < 32; j++) gp[j] = 0.0f;
#pragma unroll 1
            for (int hb = 0; hb < 8; ++hb) {
                int h = hb * 32 + tid;
                float col[32];
#pragma unroll
                for (int j = 0; j < 32; j++) col[j] = W1[j * 256 + h];
                float z0 = b1v[h], z1 = 0.0f;
                const float4* x4 = reinterpret_cast<const float4*>(sw + OFF_U);
#pragma unroll
                for (int q = 0; q < 8; q++) {
                    float4 xv = x4[q];
                    float s = xv.x * col[4 * q] + xv.y * col[4 * q + 1]
                            + xv.z * col[4 * q + 2] + xv.w * col[4 * q + 3];
                    if (q & 1) z1 += s; else z0 += s;
                }
                float th = tanhf(z0 + z1);
                float v = w2[h] * (1.0f - th * th);
#pragma unroll
                for (int j = 0; j < 32; j++) gp[j] = fmaf(v, col[j], gp[j]);
            }
            __syncwarp();
            {
                float4* md = reinterpret_cast<float4*>(sw + OFF_M + tid * 36);
#pragma unroll
                for (int q = 0; q < 8; q++)
                    md[q] = make_float4(gp[4 * q], gp[4 * q + 1], gp[4 * q + 2], gp[4 * q + 3]);
            }
            __syncwarp();
            float gs0 = 0.0f, gs1 = 0.0f;
#pragma unroll
            for (int i = 0; i < 32; i++) {
                float v = sw[OFF_M + i * 36 + tid];
                if (i & 1) gs1 += v; else gs0 += v;
            }
            g_own = gs0 + gs1;
            __syncwarp();   // OFF_M reads done before it is overwritten below
        }

        // --------------------------------------------------------------
        // Build K row in registers (a read from smem), invert in regs
        // --------------------------------------------------------------
        float mrow[32];
        {
            const float dg = (phase == 0) ? 2.0f : 1.0f;
            const float ws = (phase == 0) ? 0.75f : 1.0f;
#pragma unroll
            for (int e = 0; e < 32; e++) mrow[e] = (tid == e) ? dg : 0.0f;
#pragma unroll
            for (int r = 0; r < MCc; r++) {
                float a = sw[OFF_A + r * 36 + tid];
                if (r >= MHc) a *= ws;
                const float4* ar = reinterpret_cast<const float4*>(sw + OFF_A + r * 36);
#pragma unroll
                for (int q = 0; q < 8; q++) {
                    float4 v = ar[q];
                    mrow[4 * q + 0] = fmaf(a, v.x, mrow[4 * q + 0]);
                    mrow[4 * q + 1] = fmaf(a, v.y, mrow[4 * q + 1]);
                    mrow[4 * q + 2] = fmaf(a, v.z, mrow[4 * q + 2]);
                    mrow[4 * q + 3] = fmaf(a, v.w, mrow[4 * q + 3]);
                }
            }
        }

        gj_inv_reg(mrow, sw + OFF_R, tid);   // mrow = Kinv row tid

        // write Kinv rows to smem once (GM build needs all rows)
        {
            float4* md = reinterpret_cast<float4*>(sw + OFF_M + tid * 36);
#pragma unroll
            for (int q = 0; q < 8; q++)
                md[q] = make_float4(mrow[4 * q], mrow[4 * q + 1], mrow[4 * q + 2], mrow[4 * q + 3]);
        }
        __syncwarp();

        // --------------------------------------------------------------
        // GM row = coef * (A_src * Kinv)
        // --------------------------------------------------------------
        float GM[32];
        {
            bool act; float coef; int src;
            if (phase == 0) {
                act = (tid < 28);
                coef = (tid < MHc) ? 1.0f : (tid < MCc) ? 0.75f : -0.25f;
                src = (tid < MCc) ? tid : tid - 4;
            } else {
                act = (tid < MCc);
                coef = 1.0f;
                src = tid;
            }
#pragma unroll
            for (int e = 0; e < 32; e++) GM[e] = 0.0f;
#pragma unroll 1
            for (int jb = 0; jb < 8; jb++) {
                float4 av = make_float4(0.f, 0.f, 0.f, 0.f);
                if (act)
                    av = reinterpret_cast<const float4*>(sw + OFF_A + src * 36)[jb];
                av.x *= coef; av.y *= coef; av.z *= coef; av.w *= coef;
#pragma unroll
                for (int c = 0; c < 4; c++) {
                    int j = 4 * jb + c;
                    float a = (c == 0) ? av.x : (c == 1) ? av.y : (c == 2) ? av.z : av.w;
                    const float4* mrw = reinterpret_cast<const float4*>(sw + OFF_M + j * 36);
#pragma unroll
                    for (int q = 0; q < 8; q++) {
                        float4 v = mrw[q];
                        GM[4 * q + 0] = fmaf(a, v.x, GM[4 * q + 0]);
                        GM[4 * q + 1] = fmaf(a, v.y, GM[4 * q + 1]);
                        GM[4 * q + 2] = fmaf(a, v.z, GM[4 * q + 2]);
                        GM[4 * q + 3] = fmaf(a, v.w, GM[4 * q + 3]);
                    }
                }
            }
        }

        // --------------------------------------------------------------
        // ADMM loops. rhs is distributed by register shuffle (no smem
        // round-trip, single syncwarp per iteration); t still goes through
        // smem for the packed A^T·t matvec.
        // --------------------------------------------------------------
        if (phase == 0) {
            // Anchor: rows 0..27 (y1,t1) on lanes 0..27; rows 28..59 per-lane.
            // T[0..23] stores prescaled t (slack-folded; see R11 scheme).
            float y1 = 0.0f, t1o = 0.0f, y3 = 0.0f, t3o = 0.0f;
            u_own = 0.0f;
            const float h1 = (tid < MCc) ? b_own : 0.0f;
            if (tid < MCc) sw[OFF_T + tid] = 0.0f;
            float slack_corr = 0.0f;
#pragma unroll 1
            for (int it = 0; it <= ITc; ++it) {
                __syncwarp();
                float rhs_own;
                {
                    const ulonglong2* t2 = reinterpret_cast<const ulonglong2*>(sw + OFF_T);
                    ull ac0 = 0ull, ac1 = 0ull;
#pragma unroll
                    for (int q = 0; q < 6; q++) {
                        ulonglong2 tv = t2[q];
                        ac0 = ffma2(apk[2 * q], tv.x, ac0);
                        ac1 = ffma2(apk[2 * q + 1], tv.y, ac1);
                    }
                    float2 s0 = upk2(ac0), s1 = upk2(ac1);
                    rhs_own = xr + s0.x + s0.y + s1.x + s1.y - t3o;
                }
                // dual dot via shfl distribution of rhs
                float gu;
                {
                    float u0 = 0.0f, u1 = 0.0f, g0 = 0.0f, g1 = 0.0f;
#pragma unroll
                    for (int j = 0; j < 32; j += 2) {
                        float ra = __shfl_sync(0xffffffffu, rhs_own, j);
                        float rb = __shfl_sync(0xffffffffu, rhs_own, j + 1);
                        u0 = fmaf(mrow[j], ra, u0);
                        g0 = fmaf(GM[j], ra, g0);
                        u1 = fmaf(mrow[j + 1], rb, u1);
                        g1 = fmaf(GM[j + 1], rb, g1);
                    }
                    u_own = u0 + u1;
                    gu = g0 + g1 + slack_corr;
                }
                if (it == ITc) break;
                float w = gu + y1;
                float z = fminf(w, h1);
                y1 = w - z;
                t1o = z - y1;
                // shfl pair: lane 20+k gets t1[24+k]; lane 24+k gets t1[20+k]
                float td = __shfl_down_sync(0xffffffffu, t1o, 4);
                float tu = __shfl_up_sync(0xffffffffu, t1o, 4);
                float sv = t1o;
                slack_corr = 0.0f;
                if (tid >= MHc && tid < MCc) {
                    sv = 0.75f * t1o - 0.25f * td;
                    slack_corr = 0.25f * (t1o + td);
                } else if (tid >= MCc && tid < 28) {
                    slack_corr = 0.25f * (tu + t1o);
                }
                if (tid < MCc) sw[OFF_T + tid] = sv;
                float w3 = y3 - u_own;
                float z3 = fminf(w3, 0.0f);
                y3 = w3 - z3;
                t3o = z3 - y3;
            }
            xf_own = u_own;
            sw[OFF_U + tid] = u_own;
            __syncwarp();
        } else {
            // LMO: rows 0..23 (A, h=b) on lanes 0..23; rows 24..55 per-lane
            float y1 = 0.0f, t1o = 0.0f, y3 = 0.0f, t3o = 0.0f;
            u_own = 0.0f;
            if (tid < MCc) sw[OFF_T + tid] = 0.0f;
#pragma unroll 1
            for (int it = 0; it <= ITc; ++it) {
                __syncwarp();
                float rhs_own;
                {
                    const ulonglong2* t2 = reinterpret_cast<const ulonglong2*>(sw + OFF_T);
                    ull ac0 = 0ull, ac1 = 0ull;
#pragma unroll
                    for (int q = 0; q < 6; q++) {
                        ulonglong2 tv = t2[q];
                        ac0 = ffma2(apk[2 * q], tv.x, ac0);
                        ac1 = ffma2(apk[2 * q + 1], tv.y, ac1);
                    }
                    float2 s0 = upk2(ac0), s1 = upk2(ac1);
                    rhs_own = g_own + s0.x + s0.y + s1.x + s1.y - t3o;
                }
                {
                    float u0 = 0.0f, u1 = 0.0f, g0 = 0.0f, g1 = 0.0f;
#pragma unroll
                    for (int j = 0; j < 32; j += 2) {
                        float ra = __shfl_sync(0xffffffffu, rhs_own, j);
                        float rb = __shfl_sync(0xffffffffu, rhs_own, j + 1);
                        u0 = fmaf(mrow[j], ra, u0);
                        g0 = fmaf(GM[j], ra, g0);
                        u1 = fmaf(mrow[j + 1], rb, u1);
                        g1 = fmaf(GM[j + 1], rb, g1);
                    }
                    u_own = u0 + u1;
                    float gu = g0 + g1;
                    if (it == ITc) break;
                    float w = gu + y1;
                    float z = fminf(w, b_own);
                    y1 = w - z;
                    t1o = z - y1;
                    if (tid < MCc) sw[OFF_T + tid] = t1o;
                    float w3 = y3 - u_own;
                    float z3 = fminf(w3, 0.0f);
                    y3 = w3 - z3;
                    t3o = z3 - y3;
                }
            }
        }
    }

    // Frank-Wolfe blend
    out[(size_t)p * NVc + tid] = 0.9f * xf_own + 0.1f * u_own;
}

}  // namespace

extern "C" void kernel_launch(void* const* d_in, const int* in_sizes, int n_in,
                              void* d_out, int out_size) {
    const float* x_raw = (const float*)d_in[0];
    const float* A     = (const float*)d_in[1];
    const float* b     = (const float*)d_in[2];
    const float* W1    = (const float*)d_in[3];
    const float* b1v   = (const float*)d_in[4];
    const float* w2    = (const float*)d_in[5];
    float* out = (float*)d_out;
    int P = in_sizes[0] / 32;           // number of flattened problems
    int blocks = (P + 3) / 4;           // 4 problems (warps) per block
    fw_kernel<<<blocks, 128>>>(x_raw, A, b, W1, b1v, w2, out, P);
}

// round 15
// speedup vs baseline: 1.2219x; 1.2219x over previous
#include <cuda_runtime.h>
#include <cuda_bf16.h>
#include <math.h>

namespace {

constexpr int NVc = 32;   // x dim
constexpr int MCc = 24;   // constraint rows in A
constexpr int MHc = 20;   // hard rows
constexpr int ITc = 200;  // ADMM iterations (must match reference trajectory)

// per-warp shared layout (floats)
constexpr int OFF_A = 0;            // A: 24 rows, stride 36
constexpr int OFF_M = 864;          // M workspace: 32 x 36
constexpr int OFF_T = 2160;         // t buffer (24 used, pad 32)
constexpr int OFF_R = 2192;         // rhs (32, pad 40); also GJ pivot-row buffer
constexpr int OFF_U = 2232;         // x_feas for gradient (32, pad 40)
constexpr int WARPF = 2304;         // 9216 bytes per warp

using ull = unsigned long long;

// ---- packed f32x2 helpers (Blackwell FFMA2 path, PTX-only) ----
__device__ __forceinline__ ull pk2(float lo, float hi) {
    ull r;
    asm("mov.b64 %0, {%1, %2};" : "=l"(r) : "f"(lo), "f"(hi));
    return r;
}
__device__ __forceinline__ float2 upk2(ull v) {
    float lo, hi;
    asm("mov.b64 {%0, %1}, %2;" : "=f"(lo), "=f"(hi) : "l"(v));
    return make_float2(lo, hi);
}
__device__ __forceinline__ ull ffma2(ull a, ull b, ull c) {
    ull d;
    asm("fma.rn.f32x2 %0, %1, %2, %3;" : "=l"(d) : "l"(a), "l"(b), "l"(c));
    return d;
}

// Register-resident Gauss-Jordan inverse of SPD 32x32: lane tid owns row tid.
// buf = 32-float, 16B-aligned smem scratch for pivot-row broadcast.
__device__ __forceinline__ void gj_inv_reg(float row[32], float* buf, int tid) {
#pragma unroll
    for (int k = 0; k < 32; ++k) {
        if (tid == k) {
            float4* b4 = reinterpret_cast<float4*>(buf);
#pragma unroll
            for (int q = 0; q < 8; q++)
                b4[q] = make_float4(row[4 * q], row[4 * q + 1], row[4 * q + 2], row[4 * q + 3]);
        }
        __syncwarp();
        float rk[32];
        {
            const float4* b4 = reinterpret_cast<const float4*>(buf);
#pragma unroll
            for (int q = 0; q < 8; q++) {
                float4 v = b4[q];
                rk[4 * q] = v.x; rk[4 * q + 1] = v.y; rk[4 * q + 2] = v.z; rk[4 * q + 3] = v.w;
            }
        }
        __syncwarp();
        float piv = 1.0f / rk[k];
        float f = (row[k] - ((tid == k) ? 1.0f : 0.0f)) * piv;
#pragma unroll
        for (int j = 0; j < 32; ++j)
            row[j] = fmaf(-f, rk[j], row[j]);
        row[k] = (tid == k) ? piv : -f;
    }
}

__global__ void __launch_bounds__(128, 4)
fw_kernel(const float* __restrict__ x_raw, const float* __restrict__ Ain,
          const float* __restrict__ bin, const float* __restrict__ W1,
          const float* __restrict__ b1v, const float* __restrict__ w2,
          float* __restrict__ out, int P)
{
    __shared__ __align__(16) float smem_all[4 * WARPF];
    const int tid = threadIdx.x & 31;
    const int wid = threadIdx.x >> 5;
    const int p = blockIdx.x * 4 + wid;
    if (p >= P) return;
    float* sw = smem_all + wid * WARPF;

    // ------------------------------------------------------------------
    // Load A (smem rows + packed lane-column apk), b, x_raw
    // ------------------------------------------------------------------
    ull apk[12];   // packed pairs (A[2j][tid], A[2j+1][tid])
    {
        float tmpA[MCc];
        const float* Ap = Ain + (size_t)p * (MCc * NVc);
#pragma unroll
        for (int r = 0; r < MCc; r++) {
            float v = Ap[r * NVc + tid];
            sw[OFF_A + r * 36 + tid] = v;
            tmpA[r] = v;
        }
#pragma unroll
        for (int j = 0; j < 12; j++) apk[j] = pk2(tmpA[2 * j], tmpA[2 * j + 1]);
    }
    const float b_own = (tid < MCc) ? bin[(size_t)p * MCc + tid] : 0.0f;
    const float xr = x_raw[(size_t)p * NVc + tid];
    __syncwarp();

    float xf_own = 0.0f, u_own = 0.0f, g_own = 0.0f;

    // ==================================================================
    //  phase 0: anchor QP (Schur-reduced, Ks = A_h^T A_h + .75 A_s^T A_s + 2I)
    //  phase 1: LMO LP   (K = A^T A + I), preceded by the critic gradient
    // ==================================================================
#pragma unroll 1
    for (int phase = 0; phase < 2; ++phase) {
        if (phase == 1) {
            // ----------------------------------------------------------
            // Gradient of critic: g = W1 @ (w2 * (1 - tanh^2(x W1 + b1)))
            // ----------------------------------------------------------
            float gp[32];
#pragma unroll
            for (int j = 0; j < 32; j++) gp[j] = 0.0f;
#pragma unroll 1
            for (int hb = 0; hb < 8; ++hb) {
                int h = hb * 32 + tid;
                float col[32];
#pragma unroll
                for (int j = 0; j < 32; j++) col[j] = W1[j * 256 + h];
                float z0 = b1v[h], z1 = 0.0f;
                const float4* x4 = reinterpret_cast<const float4*>(sw + OFF_U);
#pragma unroll
                for (int q = 0; q < 8; q++) {
                    float4 xv = x4[q];
                    float s = xv.x * col[4 * q] + xv.y * col[4 * q + 1]
                            + xv.z * col[4 * q + 2] + xv.w * col[4 * q + 3];
                    if (q & 1) z1 += s; else z0 += s;
                }
                float th = tanhf(z0 + z1);
                float v = w2[h] * (1.0f - th * th);
#pragma unroll
                for (int j = 0; j < 32; j++) gp[j] = fmaf(v, col[j], gp[j]);
            }
            __syncwarp();
            {
                float4* md = reinterpret_cast<float4*>(sw + OFF_M + tid * 36);
#pragma unroll
                for (int q = 0; q < 8; q++)
                    md[q] = make_float4(gp[4 * q], gp[4 * q + 1], gp[4 * q + 2], gp[4 * q + 3]);
            }
            __syncwarp();
            float gs0 = 0.0f, gs1 = 0.0f;
#pragma unroll
            for (int i = 0; i < 32; i++) {
                float v = sw[OFF_M + i * 36 + tid];
                if (i & 1) gs1 += v; else gs0 += v;
            }
            g_own = gs0 + gs1;
            __syncwarp();   // OFF_M reads done before it is overwritten below
        }

        // --------------------------------------------------------------
        // Build K row with packed FFMA2 (lane coef from apk; A rows as
        // ulonglong2 broadcasts), then invert in registers.
        // --------------------------------------------------------------
        float mrow[32];
        {
            const float dg = (phase == 0) ? 2.0f : 1.0f;
            const float ws = (phase == 0) ? 0.75f : 1.0f;
            ull acc[16];
#pragma unroll
            for (int c = 0; c < 16; c++) {
                float lo = (tid == 2 * c)     ? dg : 0.0f;
                float hi = (tid == 2 * c + 1) ? dg : 0.0f;
                acc[c] = pk2(lo, hi);
            }
#pragma unroll
            for (int r = 0; r < MCc; r++) {
                float2 ap = upk2(apk[r >> 1]);
                float a = (r & 1) ? ap.y : ap.x;
                if (r >= MHc) a *= ws;
                ull aa = pk2(a, a);
                const ulonglong2* ar = reinterpret_cast<const ulonglong2*>(sw + OFF_A + r * 36);
#pragma unroll
                for (int q = 0; q < 8; q++) {
                    ulonglong2 v = ar[q];
                    acc[2 * q]     = ffma2(aa, v.x, acc[2 * q]);
                    acc[2 * q + 1] = ffma2(aa, v.y, acc[2 * q + 1]);
                }
            }
#pragma unroll
            for (int c = 0; c < 16; c++) {
                float2 v = upk2(acc[c]);
                mrow[2 * c] = v.x; mrow[2 * c + 1] = v.y;
            }
        }

        gj_inv_reg(mrow, sw + OFF_R, tid);   // mrow = Kinv row tid

        // write Kinv rows to smem once (GM build needs all rows)
        {
            float4* md = reinterpret_cast<float4*>(sw + OFF_M + tid * 36);
#pragma unroll
            for (int q = 0; q < 8; q++)
                md[q] = make_float4(mrow[4 * q], mrow[4 * q + 1], mrow[4 * q + 2], mrow[4 * q + 3]);
        }
        __syncwarp();

        // --------------------------------------------------------------
        // GM row = coef * (A_src * Kinv), accumulated directly in packed
        // form (gpk): Kinv rows read as ulonglong2 broadcasts.
        // --------------------------------------------------------------
        ull gpk[16];
        {
            bool act; float coef; int src;
            if (phase == 0) {
                act = (tid < 28);
                coef = (tid < MHc) ? 1.0f : (tid < MCc) ? 0.75f : -0.25f;
                src = (tid < MCc) ? tid : tid - 4;
            } else {
                act = (tid < MCc);
                coef = 1.0f;
                src = tid;
            }
#pragma unroll
            for (int c = 0; c < 16; c++) gpk[c] = 0ull;
#pragma unroll 1
            for (int jb = 0; jb < 8; jb++) {
                float4 av = make_float4(0.f, 0.f, 0.f, 0.f);
                if (act)
                    av = reinterpret_cast<const float4*>(sw + OFF_A + src * 36)[jb];
                av.x *= coef; av.y *= coef; av.z *= coef; av.w *= coef;
#pragma unroll
                for (int c = 0; c < 4; c++) {
                    int j = 4 * jb + c;
                    float a = (c == 0) ? av.x : (c == 1) ? av.y : (c == 2) ? av.z : av.w;
                    ull aa = pk2(a, a);
                    const ulonglong2* mrw = reinterpret_cast<const ulonglong2*>(sw + OFF_M + j * 36);
#pragma unroll
                    for (int q = 0; q < 8; q++) {
                        ulonglong2 v = mrw[q];
                        gpk[2 * q]     = ffma2(aa, v.x, gpk[2 * q]);
                        gpk[2 * q + 1] = ffma2(aa, v.y, gpk[2 * q + 1]);
                    }
                }
            }
        }

        // pack Kinv row into f32x2 pairs
        ull mpk[16];
#pragma unroll
        for (int c = 0; c < 16; c++)
            mpk[c] = pk2(mrow[2 * c], mrow[2 * c + 1]);

        // --------------------------------------------------------------
        // ADMM loops (packed FFMA2 dots) — identical to R11
        // --------------------------------------------------------------
        if (phase == 0) {
            // Anchor: rows 0..27 (y1,t1) on lanes 0..27; rows 28..59 per-lane.
            // T[0..23] stores prescaled t (slack-folded; see R11 scheme).
            float y1 = 0.0f, t1o = 0.0f, y3 = 0.0f, t3o = 0.0f;
            u_own = 0.0f;
            const float h1 = (tid < MCc) ? b_own : 0.0f;
            if (tid < MCc) sw[OFF_T + tid] = 0.0f;
            float slack_corr = 0.0f;
#pragma unroll 1
            for (int it = 0; it <= ITc; ++it) {
                __syncwarp();
                {
                    const ulonglong2* t2 = reinterpret_cast<const ulonglong2*>(sw + OFF_T);
                    ull ac0 = 0ull, ac1 = 0ull;
#pragma unroll
                    for (int q = 0; q < 6; q++) {
                        ulonglong2 tv = t2[q];
                        ac0 = ffma2(apk[2 * q], tv.x, ac0);
                        ac1 = ffma2(apk[2 * q + 1], tv.y, ac1);
                    }
                    float2 s0 = upk2(ac0), s1 = upk2(ac1);
                    sw[OFF_R + tid] = xr + s0.x + s0.y + s1.x + s1.y - t3o;
                }
                __syncwarp();
                float gu;
                {
                    const ulonglong2* rv2 = reinterpret_cast<const ulonglong2*>(sw + OFF_R);
                    ull au0 = 0ull, au1 = 0ull, ag0 = 0ull, ag1 = 0ull;
#pragma unroll
                    for (int q = 0; q < 8; q++) {
                        ulonglong2 rv = rv2[q];
                        au0 = ffma2(mpk[2 * q], rv.x, au0);
                        au1 = ffma2(mpk[2 * q + 1], rv.y, au1);
                        ag0 = ffma2(gpk[2 * q], rv.x, ag0);
                        ag1 = ffma2(gpk[2 * q + 1], rv.y, ag1);
                    }
                    float2 ua = upk2(au0), ub = upk2(au1), ga = upk2(ag0), gb = upk2(ag1);
                    u_own = ua.x + ua.y + ub.x + ub.y;
                    gu = ga.x + ga.y + gb.x + gb.y + slack_corr;
                }
                if (it == ITc) break;
                float w = gu + y1;
                float z = fminf(w, h1);
                y1 = w - z;
                t1o = z - y1;
                // shfl pair: lane 20+k gets t1[24+k]; lane 24+k gets t1[20+k]
                float td = __shfl_down_sync(0xffffffffu, t1o, 4);
                float tu = __shfl_up_sync(0xffffffffu, t1o, 4);
                float sv = t1o;
                slack_corr = 0.0f;
                if (tid >= MHc && tid < MCc) {
                    sv = 0.75f * t1o - 0.25f * td;
                    slack_corr = 0.25f * (t1o + td);
                } else if (tid >= MCc && tid < 28) {
                    slack_corr = 0.25f * (tu + t1o);
                }
                if (tid < MCc) sw[OFF_T + tid] = sv;
                float w3 = y3 - u_own;
                float z3 = fminf(w3, 0.0f);
                y3 = w3 - z3;
                t3o = z3 - y3;
            }
            xf_own = u_own;
            sw[OFF_U + tid] = u_own;
            __syncwarp();
        } else {
            // LMO: rows 0..23 (A, h=b) on lanes 0..23; rows 24..55 per-lane
            float y1 = 0.0f, t1o = 0.0f, y3 = 0.0f, t3o = 0.0f;
            u_own = 0.0f;
            if (tid < MCc) sw[OFF_T + tid] = 0.0f;
#pragma unroll 1
            for (int it = 0; it <= ITc; ++it) {
                __syncwarp();
                {
                    const ulonglong2* t2 = reinterpret_cast<const ulonglong2*>(sw + OFF_T);
                    ull ac0 = 0ull, ac1 = 0ull;
#pragma unroll
                    for (int q = 0; q < 6; q++) {
                        ulonglong2 tv = t2[q];
                        ac0 = ffma2(apk[2 * q], tv.x, ac0);
                        ac1 = ffma2(apk[2 * q + 1], tv.y, ac1);
                    }
                    float2 s0 = upk2(ac0), s1 = upk2(ac1);
                    sw[OFF_R + tid] = g_own + s0.x + s0.y + s1.x + s1.y - t3o;
                }
                __syncwarp();
                {
                    const ulonglong2* rv2 = reinterpret_cast<const ulonglong2*>(sw + OFF_R);
                    ull au0 = 0ull, au1 = 0ull, ag0 = 0ull, ag1 = 0ull;
#pragma unroll
                    for (int q = 0; q < 8; q++) {
                        ulonglong2 rv = rv2[q];
                        au0 = ffma2(mpk[2 * q], rv.x, au0);
                        au1 = ffma2(mpk[2 * q + 1], rv.y, au1);
                        ag0 = ffma2(gpk[2 * q], rv.x, ag0);
                        ag1 = ffma2(gpk[2 * q + 1], rv.y, ag1);
                    }
                    float2 ua = upk2(au0), ub = upk2(au1), ga = upk2(ag0), gb = upk2(ag1);
                    u_own = ua.x + ua.y + ub.x + ub.y;
                    float gu = ga.x + ga.y + gb.x + gb.y;
                    if (it == ITc) break;
                    float w = gu + y1;
                    float z = fminf(w, b_own);
                    y1 = w - z;
                    t1o = z - y1;
                    if (tid < MCc) sw[OFF_T + tid] = t1o;
                    float w3 = y3 - u_own;
                    float z3 = fminf(w3, 0.0f);
                    y3 = w3 - z3;
                    t3o = z3 - y3;
                }
            }
        }
    }

    // Frank-Wolfe blend
    out[(size_t)p * NVc + tid] = 0.9f * xf_own + 0.1f * u_own;
}

}  // namespace

extern "C" void kernel_launch(void* const* d_in, const int* in_sizes, int n_in,
                              void* d_out, int out_size) {
    const float* x_raw = (const float*)d_in[0];
    const float* A     = (const float*)d_in[1];
    const float* b     = (const float*)d_in[2];
    const float* W1    = (const float*)d_in[3];
    const float* b1v   = (const float*)d_in[4];
    const float* w2    = (const float*)d_in[5];
    float* out = (float*)d_out;
    int P = in_sizes[0] / 32;           // number of flattened problems
    int blocks = (P + 3) / 4;           // 4 problems (warps) per block
    fw_kernel<<<blocks, 128>>>(x_raw, A, b, W1, b1v, w2, out, P);
}

// round 16
// speedup vs baseline: 1.2293x; 1.0061x over previous
#include <cuda_runtime.h>
#include <cuda_bf16.h>
#include <math.h>

namespace {

constexpr int NVc = 32;   // x dim
constexpr int MCc = 24;   // constraint rows in A
constexpr int MHc = 20;   // hard rows
constexpr int ITc = 200;  // ADMM iterations (must match reference trajectory)
constexpr int MAXP = 16384;  // problem count (4096 x 4, fixed shapes)

// per-warp shared layout (floats)
constexpr int OFF_A = 0;            // A: 24 rows, stride 36
constexpr int OFF_M = 864;          // M workspace: 32 x 36
constexpr int OFF_T = 2160;         // t buffer (24 used, pad 32)
constexpr int OFF_R = 2192;         // rhs (32, pad 40); also GJ pivot-row buffer
constexpr int OFF_U = 2232;         // x_feas for gradient (32, pad 40)
constexpr int WARPF = 2304;         // 9216 bytes per warp

using ull = unsigned long long;

// cross-phase scratch: K_lmo row stash, transposed layout so each lane
// reads back exactly the elements it wrote (no inter-thread communication).
__device__ float g_klmo[(size_t)MAXP * 1024];

// ---- packed f32x2 helpers (Blackwell FFMA2 path, PTX-only) ----
__device__ __forceinline__ ull pk2(float lo, float hi) {
    ull r;
    asm("mov.b64 %0, {%1, %2};" : "=l"(r) : "f"(lo), "f"(hi));
    return r;
}
__device__ __forceinline__ float2 upk2(ull v) {
    float lo, hi;
    asm("mov.b64 {%0, %1}, %2;" : "=f"(lo), "=f"(hi) : "l"(v));
    return make_float2(lo, hi);
}
__device__ __forceinline__ ull ffma2(ull a, ull b, ull c) {
    ull d;
    asm("fma.rn.f32x2 %0, %1, %2, %3;" : "=l"(d) : "l"(a), "l"(b), "l"(c));
    return d;
}

// Register-resident Gauss-Jordan inverse of SPD 32x32: lane tid owns row tid.
// buf = 32-float, 16B-aligned smem scratch for pivot-row broadcast.
__device__ __forceinline__ void gj_inv_reg(float row[32], float* buf, int tid) {
#pragma unroll
    for (int k = 0; k < 32; ++k) {
        if (tid == k) {
            float4* b4 = reinterpret_cast<float4*>(buf);
#pragma unroll
            for (int q = 0; q < 8; q++)
                b4[q] = make_float4(row[4 * q], row[4 * q + 1], row[4 * q + 2], row[4 * q + 3]);
        }
        __syncwarp();
        float rk[32];
        {
            const float4* b4 = reinterpret_cast<const float4*>(buf);
#pragma unroll
            for (int q = 0; q < 8; q++) {
                float4 v = b4[q];
                rk[4 * q] = v.x; rk[4 * q + 1] = v.y; rk[4 * q + 2] = v.z; rk[4 * q + 3] = v.w;
            }
        }
        __syncwarp();
        float piv = 1.0f / rk[k];
        float f = (row[k] - ((tid == k) ? 1.0f : 0.0f)) * piv;
#pragma unroll
        for (int j = 0; j < 32; ++j)
            row[j] = fmaf(-f, rk[j], row[j]);
        row[k] = (tid == k) ? piv : -f;
    }
}

__global__ void __launch_bounds__(128, 4)
fw_kernel(const float* __restrict__ x_raw, const float* __restrict__ Ain,
          const float* __restrict__ bin, const float* __restrict__ W1,
          const float* __restrict__ b1v, const float* __restrict__ w2,
          float* __restrict__ out, int P)
{
    __shared__ __align__(16) float smem_all[4 * WARPF];
    const int tid = threadIdx.x & 31;
    const int wid = threadIdx.x >> 5;
    const int p = blockIdx.x * 4 + wid;
    if (p >= P) return;
    float* sw = smem_all + wid * WARPF;

    // ------------------------------------------------------------------
    // Load A (smem rows + packed lane-column apk), b, x_raw
    // ------------------------------------------------------------------
    ull apk[12];   // packed pairs (A[2j][tid], A[2j+1][tid])
    {
        float tmpA[MCc];
        const float* Ap = Ain + (size_t)p * (MCc * NVc);
#pragma unroll
        for (int r = 0; r < MCc; r++) {
            float v = Ap[r * NVc + tid];
            sw[OFF_A + r * 36 + tid] = v;
            tmpA[r] = v;
        }
#pragma unroll
        for (int j = 0; j < 12; j++) apk[j] = pk2(tmpA[2 * j], tmpA[2 * j + 1]);
    }
    const float b_own = (tid < MCc) ? bin[(size_t)p * MCc + tid] : 0.0f;
    const float xr = x_raw[(size_t)p * NVc + tid];
    __syncwarp();

    float xf_own = 0.0f, u_own = 0.0f, g_own = 0.0f;

    // ==================================================================
    //  phase 0: anchor QP (Schur-reduced, Ks = A_h^T A_h + .75 A_s^T A_s + 2I)
    //  phase 1: LMO LP   (K = A^T A + I = Ks + 0.25 A_s^T A_s - I, stashed)
    // ==================================================================
#pragma unroll 1
    for (int phase = 0; phase < 2; ++phase) {
        if (phase == 1) {
            // ----------------------------------------------------------
            // Gradient of critic: g = W1 @ (w2 * (1 - tanh^2(x W1 + b1)))
            // ----------------------------------------------------------
            float gp[32];
#pragma unroll
            for (int j = 0; j < 32; j++) gp[j] = 0.0f;
#pragma unroll 1
            for (int hb = 0; hb < 8; ++hb) {
                int h = hb * 32 + tid;
                float col[32];
#pragma unroll
                for (int j = 0; j < 32; j++) col[j] = W1[j * 256 + h];
                float z0 = b1v[h], z1 = 0.0f;
                const float4* x4 = reinterpret_cast<const float4*>(sw + OFF_U);
#pragma unroll
                for (int q = 0; q < 8; q++) {
                    float4 xv = x4[q];
                    float s = xv.x * col[4 * q] + xv.y * col[4 * q + 1]
                            + xv.z * col[4 * q + 2] + xv.w * col[4 * q + 3];
                    if (q & 1) z1 += s; else z0 += s;
                }
                float th = tanhf(z0 + z1);
                float v = w2[h] * (1.0f - th * th);
#pragma unroll
                for (int j = 0; j < 32; j++) gp[j] = fmaf(v, col[j], gp[j]);
            }
            __syncwarp();
            {
                float4* md = reinterpret_cast<float4*>(sw + OFF_M + tid * 36);
#pragma unroll
                for (int q = 0; q < 8; q++)
                    md[q] = make_float4(gp[4 * q], gp[4 * q + 1], gp[4 * q + 2], gp[4 * q + 3]);
            }
            __syncwarp();
            float gs0 = 0.0f, gs1 = 0.0f;
#pragma unroll
            for (int i = 0; i < 32; i++) {
                float v = sw[OFF_M + i * 36 + tid];
                if (i & 1) gs1 += v; else gs0 += v;
            }
            g_own = gs0 + gs1;
            __syncwarp();   // OFF_M reads done before it is overwritten below
        }

        // --------------------------------------------------------------
        // K row: phase 0 builds Ks (packed FFMA2) and stashes the K_lmo
        // row (= Ks + 0.25 A_s^T A_s - I) to global scratch; phase 1
        // simply reloads it (32 coalesced LDG, same-lane data).
        // --------------------------------------------------------------
        float mrow[32];
        if (phase == 0) {
            ull acc[16], accS[16];
#pragma unroll
            for (int c = 0; c < 16; c++) {
                float lo = (tid == 2 * c)     ? 2.0f : 0.0f;
                float hi = (tid == 2 * c + 1) ? 2.0f : 0.0f;
                acc[c] = pk2(lo, hi);
                accS[c] = 0ull;
            }
#pragma unroll
            for (int r = 0; r < MCc; r++) {
                float2 ap = upk2(apk[r >> 1]);
                float a0 = (r & 1) ? ap.y : ap.x;      // original coefficient
                float a = (r >= MHc) ? 0.75f * a0 : a0;
                ull aa = pk2(a, a);
                ull as = (r >= MHc) ? pk2(0.25f * a0, 0.25f * a0) : 0ull;
                const ulonglong2* ar = reinterpret_cast<const ulonglong2*>(sw + OFF_A + r * 36);
#pragma unroll
                for (int q = 0; q < 8; q++) {
                    ulonglong2 v = ar[q];
                    acc[2 * q]     = ffma2(aa, v.x, acc[2 * q]);
                    acc[2 * q + 1] = ffma2(aa, v.y, acc[2 * q + 1]);
                    if (r >= MHc) {
                        accS[2 * q]     = ffma2(as, v.x, accS[2 * q]);
                        accS[2 * q + 1] = ffma2(as, v.y, accS[2 * q + 1]);
                    }
                }
            }
            float* scr = g_klmo + (size_t)p * 1024;
#pragma unroll
            for (int c = 0; c < 16; c++) {
                float2 av = upk2(acc[c]);
                float2 sv = upk2(accS[c]);
                mrow[2 * c]     = av.x;
                mrow[2 * c + 1] = av.y;
                float lo = av.x + sv.x - ((tid == 2 * c)     ? 1.0f : 0.0f);
                float hi = av.y + sv.y - ((tid == 2 * c + 1) ? 1.0f : 0.0f);
                scr[(2 * c) * 32 + tid]     = lo;
                scr[(2 * c + 1) * 32 + tid] = hi;
            }
        } else {
            const float* scr = g_klmo + (size_t)p * 1024;
#pragma unroll
            for (int j = 0; j < 32; j++)
                mrow[j] = scr[j * 32 + tid];
        }

        gj_inv_reg(mrow, sw + OFF_R, tid);   // mrow = Kinv row tid

        // write Kinv rows to smem once (GM build needs all rows)
        {
            float4* md = reinterpret_cast<float4*>(sw + OFF_M + tid * 36);
#pragma unroll
            for (int q = 0; q < 8; q++)
                md[q] = make_float4(mrow[4 * q], mrow[4 * q + 1], mrow[4 * q + 2], mrow[4 * q + 3]);
        }
        __syncwarp();

        // --------------------------------------------------------------
        // GM row = coef * (A_src * Kinv), accumulated directly in packed
        // form (gpk): Kinv rows read as ulonglong2 broadcasts.
        // --------------------------------------------------------------
        ull gpk[16];
        {
            bool act; float coef; int src;
            if (phase == 0) {
                act = (tid < 28);
                coef = (tid < MHc) ? 1.0f : (tid < MCc) ? 0.75f : -0.25f;
                src = (tid < MCc) ? tid : tid - 4;
            } else {
                act = (tid < MCc);
                coef = 1.0f;
                src = tid;
            }
#pragma unroll
            for (int c = 0; c < 16; c++) gpk[c] = 0ull;
#pragma unroll 1
            for (int jb = 0; jb < 8; jb++) {
                float4 av = make_float4(0.f, 0.f, 0.f, 0.f);
                if (act)
                    av = reinterpret_cast<const float4*>(sw + OFF_A + src * 36)[jb];
                av.x *= coef; av.y *= coef; av.z *= coef; av.w *= coef;
#pragma unroll
                for (int c = 0; c < 4; c++) {
                    int j = 4 * jb + c;
                    float a = (c == 0) ? av.x : (c == 1) ? av.y : (c == 2) ? av.z : av.w;
                    ull aa = pk2(a, a);
                    const ulonglong2* mrw = reinterpret_cast<const ulonglong2*>(sw + OFF_M + j * 36);
#pragma unroll
                    for (int q = 0; q < 8; q++) {
                        ulonglong2 v = mrw[q];
                        gpk[2 * q]     = ffma2(aa, v.x, gpk[2 * q]);
                        gpk[2 * q + 1] = ffma2(aa, v.y, gpk[2 * q + 1]);
                    }
                }
            }
        }

        // pack Kinv row into f32x2 pairs
        ull mpk[16];
#pragma unroll
        for (int c = 0; c < 16; c++)
            mpk[c] = pk2(mrow[2 * c], mrow[2 * c + 1]);

        // --------------------------------------------------------------
        // ADMM loops (packed FFMA2 dots) — identical to R11/R15
        // --------------------------------------------------------------
        if (phase == 0) {
            // Anchor: rows 0..27 (y1,t1) on lanes 0..27; rows 28..59 per-lane.
            // T[0..23] stores prescaled t (slack-folded; see R11 scheme).
            float y1 = 0.0f, t1o = 0.0f, y3 = 0.0f, t3o = 0.0f;
            u_own = 0.0f;
            const float h1 = (tid < MCc) ? b_own : 0.0f;
            if (tid < MCc) sw[OFF_T + tid] = 0.0f;
            float slack_corr = 0.0f;
#pragma unroll 1
            for (int it = 0; it <= ITc; ++it) {
                __syncwarp();
                {
                    const ulonglong2* t2 = reinterpret_cast<const ulonglong2*>(sw + OFF_T);
                    ull ac0 = 0ull, ac1 = 0ull;
#pragma unroll
                    for (int q = 0; q < 6; q++) {
                        ulonglong2 tv = t2[q];
                        ac0 = ffma2(apk[2 * q], tv.x, ac0);
                        ac1 = ffma2(apk[2 * q + 1], tv.y, ac1);
                    }
                    float2 s0 = upk2(ac0), s1 = upk2(ac1);
                    sw[OFF_R + tid] = xr + s0.x + s0.y + s1.x + s1.y - t3o;
                }
                __syncwarp();
                float gu;
                {
                    const ulonglong2* rv2 = reinterpret_cast<const ulonglong2*>(sw + OFF_R);
                    ull au0 = 0ull, au1 = 0ull, ag0 = 0ull, ag1 = 0ull;
#pragma unroll
                    for (int q = 0; q < 8; q++) {
                        ulonglong2 rv = rv2[q];
                        au0 = ffma2(mpk[2 * q], rv.x, au0);
                        au1 = ffma2(mpk[2 * q + 1], rv.y, au1);
                        ag0 = ffma2(gpk[2 * q], rv.x, ag0);
                        ag1 = ffma2(gpk[2 * q + 1], rv.y, ag1);
                    }
                    float2 ua = upk2(au0), ub = upk2(au1), ga = upk2(ag0), gb = upk2(ag1);
                    u_own = ua.x + ua.y + ub.x + ub.y;
                    gu = ga.x + ga.y + gb.x + gb.y + slack_corr;
                }
                if (it == ITc) break;
                float w = gu + y1;
                float z = fminf(w, h1);
                y1 = w - z;
                t1o = z - y1;
                // shfl pair: lane 20+k gets t1[24+k]; lane 24+k gets t1[20+k]
                float td = __shfl_down_sync(0xffffffffu, t1o, 4);
                float tu = __shfl_up_sync(0xffffffffu, t1o, 4);
                float sv = t1o;
                slack_corr = 0.0f;
                if (tid >= MHc && tid < MCc) {
                    sv = 0.75f * t1o - 0.25f * td;
                    slack_corr = 0.25f * (t1o + td);
                } else if (tid >= MCc && tid < 28) {
                    slack_corr = 0.25f * (tu + t1o);
                }
                if (tid < MCc) sw[OFF_T + tid] = sv;
                float w3 = y3 - u_own;
                float z3 = fminf(w3, 0.0f);
                y3 = w3 - z3;
                t3o = z3 - y3;
            }
            xf_own = u_own;
            sw[OFF_U + tid] = u_own;
            __syncwarp();
        } else {
            // LMO: rows 0..23 (A, h=b) on lanes 0..23; rows 24..55 per-lane
            float y1 = 0.0f, t1o = 0.0f, y3 = 0.0f, t3o = 0.0f;
            u_own = 0.0f;
            if (tid < MCc) sw[OFF_T + tid] = 0.0f;
#pragma unroll 1
            for (int it = 0; it <= ITc; ++it) {
                __syncwarp();
                {
                    const ulonglong2* t2 = reinterpret_cast<const ulonglong2*>(sw + OFF_T);
                    ull ac0 = 0ull, ac1 = 0ull;
#pragma unroll
                    for (int q = 0; q < 6; q++) {
                        ulonglong2 tv = t2[q];
                        ac0 = ffma2(apk[2 * q], tv.x, ac0);
                        ac1 = ffma2(apk[2 * q + 1], tv.y, ac1);
                    }
                    float2 s0 = upk2(ac0), s1 = upk2(ac1);
                    sw[OFF_R + tid] = g_own + s0.x + s0.y + s1.x + s1.y - t3o;
                }
                __syncwarp();
                {
                    const ulonglong2* rv2 = reinterpret_cast<const ulonglong2*>(sw + OFF_R);
                    ull au0 = 0ull, au1 = 0ull, ag0 = 0ull, ag1 = 0ull;
#pragma unroll
                    for (int q = 0; q < 8; q++) {
                        ulonglong2 rv = rv2[q];
                        au0 = ffma2(mpk[2 * q], rv.x, au0);
                        au1 = ffma2(mpk[2 * q + 1], rv.y, au1);
                        ag0 = ffma2(gpk[2 * q], rv.x, ag0);
                        ag1 = ffma2(gpk[2 * q + 1], rv.y, ag1);
                    }
                    float2 ua = upk2(au0), ub = upk2(au1), ga = upk2(ag0), gb = upk2(ag1);
                    u_own = ua.x + ua.y + ub.x + ub.y;
                    float gu = ga.x + ga.y + gb.x + gb.y;
                    if (it == ITc) break;
                    float w = gu + y1;
                    float z = fminf(w, b_own);
                    y1 = w - z;
                    t1o = z - y1;
                    if (tid < MCc) sw[OFF_T + tid] = t1o;
                    float w3 = y3 - u_own;
                    float z3 = fminf(w3, 0.0f);
                    y3 = w3 - z3;
                    t3o = z3 - y3;
                }
            }
        }
    }

    // Frank-Wolfe blend
    out[(size_t)p * NVc + tid] = 0.9f * xf_own + 0.1f * u_own;
}

}  // namespace

extern "C" void kernel_launch(void* const* d_in, const int* in_sizes, int n_in,
                              void* d_out, int out_size) {
    const float* x_raw = (const float*)d_in[0];
    const float* A     = (const float*)d_in[1];
    const float* b     = (const float*)d_in[2];
    const float* W1    = (const float*)d_in[3];
    const float* b1v   = (const float*)d_in[4];
    const float* w2    = (const float*)d_in[5];
    float* out = (float*)d_out;
    int P = in_sizes[0] / 32;           // number of flattened problems
    int blocks = (P + 3) / 4;           // 4 problems (warps) per block
    fw_kernel<<<blocks, 128>>>(x_raw, A, b, W1, b1v, w2, out, P);
}